// round 14
// baseline (speedup 1.0000x reference)
#include <cuda_runtime.h>
#include <cuda_fp16.h>
#include <math.h>
#include <stdint.h>

// Problem constants
#define Bb 4
#define Tt 1024
#define Cc 1024
#define Hh 16
#define HSs 64
#define Ll 12
#define Vv 50304
#define Mm (Bb*Tt)      // 4096
#define FFd (4*Cc)      // 4096

typedef __half h16;

// ---------------- scratch (static device memory; no allocations) ----------------
__device__ float g_x[(size_t)Mm*Cc];
__device__ float g_rowloss[Mm];
__device__ h16 g_hhi[(size_t)Mm*Cc];
__device__ h16 g_hlo[(size_t)Mm*Cc];
__device__ h16 g_qkvhi[(size_t)Mm*3072];
__device__ h16 g_qkvlo[(size_t)Mm*3072];
__device__ h16 g_atthi[(size_t)Mm*Cc];
__device__ h16 g_attlo[(size_t)Mm*Cc];
__device__ h16 g_ffhhi[(size_t)Mm*FFd];
__device__ h16 g_ffhlo[(size_t)Mm*FFd];
__device__ h16 g_whi[(size_t)Vv*Cc];
__device__ h16 g_wlo[(size_t)Vv*Cc];

// ---------------- PTX helpers (portable, no arch-a gating) ----------------
__device__ __forceinline__ uint32_t smem_u32(const void* p) {
    uint32_t a;
    asm("{ .reg .u64 t; cvta.to.shared.u64 t, %1; cvt.u32.u64 %0, t; }" : "=r"(a) : "l"(p));
    return a;
}
__device__ __forceinline__ void ldsm4(uint32_t* r, uint32_t a) {
    asm volatile("ldmatrix.sync.aligned.m8n8.x4.shared.b16 {%0,%1,%2,%3}, [%4];"
        : "=r"(r[0]), "=r"(r[1]), "=r"(r[2]), "=r"(r[3]) : "r"(a));
}
__device__ __forceinline__ void ldsm4t(uint32_t* r, uint32_t a) {
    asm volatile("ldmatrix.sync.aligned.m8n8.x4.trans.shared.b16 {%0,%1,%2,%3}, [%4];"
        : "=r"(r[0]), "=r"(r[1]), "=r"(r[2]), "=r"(r[3]) : "r"(a));
}
// fp16 inputs, fp32 accumulator (half-rate "main" term)
__device__ __forceinline__ void mmaF(float* c, const uint32_t* a, uint32_t b0, uint32_t b1) {
    asm volatile("mma.sync.aligned.m16n8k16.row.col.f32.f16.f16.f32 "
        "{%0,%1,%2,%3}, {%4,%5,%6,%7}, {%8,%9}, {%0,%1,%2,%3};"
        : "+f"(c[0]), "+f"(c[1]), "+f"(c[2]), "+f"(c[3])
        : "r"(a[0]), "r"(a[1]), "r"(a[2]), "r"(a[3]), "r"(b0), "r"(b1));
}
// fp16 inputs, fp16 accumulator (full-rate "correction" terms)
__device__ __forceinline__ void mmaH(uint32_t* c, const uint32_t* a, uint32_t b0, uint32_t b1) {
    asm volatile("mma.sync.aligned.m16n8k16.row.col.f16.f16.f16.f16 "
        "{%0,%1}, {%2,%3,%4,%5}, {%6,%7}, {%0,%1};"
        : "+r"(c[0]), "+r"(c[1])
        : "r"(a[0]), "r"(a[1]), "r"(a[2]), "r"(a[3]), "r"(b0), "r"(b1));
}
__device__ __forceinline__ void cpa16(uint32_t saddr, const void* g) {
    asm volatile("cp.async.cg.shared.global [%0], [%1], 16;" :: "r"(saddr), "l"(g));
}
#define CPCOMMIT() asm volatile("cp.async.commit_group;" ::: "memory")
#define CPWAIT0()  asm volatile("cp.async.wait_group 0;" ::: "memory")

__device__ __forceinline__ float ex2f(float x) {
    float y; asm("ex2.approx.f32 %0, %1;" : "=f"(y) : "f"(x)); return y;
}
__device__ __forceinline__ void split2(float x, h16& h, h16& l) {
    h = __float2half_rn(x);
    l = __float2half_rn(x - __half2float(h));
}
__device__ __forceinline__ uint32_t packh(h16 a, h16 b) {
    return (uint32_t)__half_as_ushort(a) | ((uint32_t)__half_as_ushort(b) << 16);
}
__device__ __forceinline__ uint32_t splitpack(float x0, float x1, uint32_t& lo) {
    h16 h0,l0,h1,l1;
    split2(x0,h0,l0); split2(x1,h1,l1);
    lo = packh(l0,l1);
    return packh(h0,h1);
}
__device__ __forceinline__ float2 h2f2(uint32_t r) {
    __half2 h = *(__half2*)&r;
    return __half22float2(h);
}

// ---------------- helpers ----------------
__device__ __forceinline__ float block_reduce(float v, float* buf, bool ismax) {
    int tid = threadIdx.x;            // blockDim.x == 256
    buf[tid] = v;
    __syncthreads();
    #pragma unroll
    for (int s = 128; s > 0; s >>= 1) {
        if (tid < s) buf[tid] = ismax ? fmaxf(buf[tid], buf[tid + s]) : (buf[tid] + buf[tid + s]);
        __syncthreads();
    }
    float r = buf[0];
    __syncthreads();
    return r;
}

// ---------------- embed ----------------
__global__ void embed_k(const int* __restrict__ idx, const float* __restrict__ tok,
                        const float* __restrict__ pos, float* __restrict__ x) {
    int i4 = blockIdx.x * blockDim.x + threadIdx.x;
    if (i4 >= Mm * Cc / 4) return;
    int c  = (i4 % (Cc / 4)) * 4;
    int bt = i4 / (Cc / 4);
    int t  = bt % Tt;
    int tk = idx[bt];
    float4 a = *(const float4*)&tok[(size_t)tk * Cc + c];
    float4 p = *(const float4*)&pos[(size_t)t * Cc + c];
    a.x += p.x; a.y += p.y; a.z += p.z; a.w += p.w;
    *(float4*)&x[(size_t)bt * Cc + c] = a;
}

// ---------------- layernorm: fp32 in, f16 hi/lo out ----------------
__global__ void layernorm_split_k(const float* __restrict__ x, const float* __restrict__ g,
                                  const float* __restrict__ b,
                                  h16* __restrict__ yhi, h16* __restrict__ ylo) {
    __shared__ float buf[256];
    int tid = threadIdx.x;
    const float* xr = x + (size_t)blockIdx.x * Cc;
    float4 v = ((const float4*)xr)[tid];
    float s  = v.x + v.y + v.z + v.w;
    float sq = v.x*v.x + v.y*v.y + v.z*v.z + v.w*v.w;
    s  = block_reduce(s,  buf, false);
    sq = block_reduce(sq, buf, false);
    float mean = s * (1.0f / Cc);
    float var  = sq * (1.0f / Cc) - mean * mean;
    float r    = rsqrtf(var + 1e-5f);
    float4 gg = ((const float4*)g)[tid];
    float4 bb = ((const float4*)b)[tid];
    float o0 = (v.x - mean) * r * gg.x + bb.x;
    float o1 = (v.y - mean) * r * gg.y + bb.y;
    float o2 = (v.z - mean) * r * gg.z + bb.z;
    float o3 = (v.w - mean) * r * gg.w + bb.w;
    uint2 wh, wl;
    wh.x = splitpack(o0, o1, wl.x);
    wh.y = splitpack(o2, o3, wl.y);
    ((uint2*)(yhi + (size_t)blockIdx.x * Cc))[tid] = wh;
    ((uint2*)(ylo + (size_t)blockIdx.x * Cc))[tid] = wl;
}

// ---------------- W [K,N] fp32 -> transposed [N,K] f16 hi/lo at row offset ----------------
__global__ void conv_wT_k(const float* __restrict__ W, int K, int N, int n_off,
                          h16* __restrict__ hi, h16* __restrict__ lo) {
    __shared__ float t[32][33];
    int n0 = blockIdx.x * 32, k0 = blockIdx.y * 32;
    int tx = threadIdx.x & 31, ty = threadIdx.x >> 5;   // 256 threads: 32 x 8
    #pragma unroll
    for (int i = 0; i < 32; i += 8)
        t[ty + i][tx] = W[(size_t)(k0 + ty + i) * N + n0 + tx];
    __syncthreads();
    #pragma unroll
    for (int i = 0; i < 32; i += 8) {
        int n = ty + i;
        float x = t[tx][n];                          // W[k0+tx][n0+n]
        h16 h, l;
        split2(x, h, l);
        hi[(size_t)(n_off + n0 + n) * K + k0 + tx] = h;
        lo[(size_t)(n_off + n0 + n) * K + k0 + tx] = l;
    }
}

// QKV weights: 3 convs in one launch (z selects the matrix)
__global__ void conv_wqkv_k(const float* __restrict__ Wq, const float* __restrict__ Wk,
                            const float* __restrict__ Wv,
                            h16* __restrict__ hi, h16* __restrict__ lo) {
    __shared__ float t[32][33];
    const float* W = (blockIdx.z == 0) ? Wq : (blockIdx.z == 1) ? Wk : Wv;
    int n_off = blockIdx.z * 1024;
    int n0 = blockIdx.x * 32, k0 = blockIdx.y * 32;
    int tx = threadIdx.x & 31, ty = threadIdx.x >> 5;
    #pragma unroll
    for (int i = 0; i < 32; i += 8)
        t[ty + i][tx] = W[(size_t)(k0 + ty + i) * Cc + n0 + tx];
    __syncthreads();
    #pragma unroll
    for (int i = 0; i < 32; i += 8) {
        int n = ty + i;
        float x = t[tx][n];
        h16 h, l;
        split2(x, h, l);
        hi[(size_t)(n_off + n0 + n) * Cc + k0 + tx] = h;
        lo[(size_t)(n_off + n0 + n) * Cc + k0 + tx] = l;
    }
}

// ---------------- fp16x3 tensor-core GEMM ----------------
// main term f32-acc (half-rate), corrections f16-acc (full-rate).
// CTA 128x128, 512 threads = 16 warps of 32x32. BK=32, 2-stage cp.async, 1 sync/chunk.
#define BKh      32
#define ROWH     40
#define ARR_B    (128 * ROWH * 2)      // 10240 B
#define STAGE_B  (4 * ARR_B)           // 40960 B
#define GEMM_SMEM (2 * STAGE_B)        // 81920 B

__device__ __forceinline__ void issue_stage(
    uint32_t sbase, int buf, int tid, int rowBase, int colBase, int K, int k0,
    const h16* __restrict__ Ahi, const h16* __restrict__ Alo,
    const h16* __restrict__ Bhi, const h16* __restrict__ Blo)
{
    // 512 threads: each loads one 16B seg per array (row = tid>>2, seg = tid&3)
    const int row = tid >> 2;
    const int c8  = (tid & 3) << 3;
    uint32_t sb = sbase + (uint32_t)buf * STAGE_B;
    uint32_t soff = (row * ROWH + c8) * 2;
    cpa16(sb + 0 * ARR_B + soff, Ahi + (size_t)(rowBase + row) * K + k0 + c8);
    cpa16(sb + 1 * ARR_B + soff, Alo + (size_t)(rowBase + row) * K + k0 + c8);
    cpa16(sb + 2 * ARR_B + soff, Bhi + (size_t)(colBase + row) * K + k0 + c8);
    cpa16(sb + 3 * ARR_B + soff, Blo + (size_t)(colBase + row) * K + k0 + c8);
}

template<bool SPLIT, bool BIAS, bool RES, bool RELU>
__global__ void __launch_bounds__(512) gemm_tc(
    int K,
    const h16* __restrict__ Ahi, const h16* __restrict__ Alo,
    const h16* __restrict__ Bhi, const h16* __restrict__ Blo,
    const float* __restrict__ bias, const float* __restrict__ res, int ldr,
    float* __restrict__ C, h16* __restrict__ Chi, h16* __restrict__ Clo, int ldc)
{
    extern __shared__ __align__(16) char smem[];
    const uint32_t sbase = smem_u32(smem);
    const int tid  = threadIdx.x;
    const int lane = tid & 31;
    const int warp = tid >> 5;
    const int m0 = (warp & 3) * 32, n0 = (warp >> 2) * 32;   // 4x4 warp grid
    const int rowBase = blockIdx.y * 128;
    const int colBase = blockIdx.x * 128;

    float accF[2][4][4];
    uint32_t accH[2][4][2];
    #pragma unroll
    for (int i = 0; i < 2; ++i)
        #pragma unroll
        for (int j = 0; j < 4; ++j) {
            #pragma unroll
            for (int q = 0; q < 4; ++q) accF[i][j][q] = 0.f;
            accH[i][j][0] = 0u; accH[i][j][1] = 0u;
        }

    const int NC = K / BKh;

    issue_stage(sbase, 0, tid, rowBase, colBase, K, 0, Ahi, Alo, Bhi, Blo);
    CPCOMMIT();

    const int lr16 = lane & 15;
    const int lk8  = (lane >> 4) << 3;
    uint32_t offA[2], offB[2];
    #pragma unroll
    for (int i = 0; i < 2; ++i) {
        offA[i] = ((m0 + i * 16 + lr16) * ROWH + lk8) * 2;
        offB[i] = ((n0 + i * 16 + lr16) * ROWH + lk8) * 2;
    }

    for (int c = 0; c < NC; ++c) {
        CPWAIT0();
        __syncthreads();
        if (c + 1 < NC) {
            issue_stage(sbase, (c + 1) & 1, tid, rowBase, colBase, K, (c + 1) * BKh,
                        Ahi, Alo, Bhi, Blo);
            CPCOMMIT();
        }
        const uint32_t st = sbase + (uint32_t)(c & 1) * STAGE_B;

        #pragma unroll
        for (int ks = 0; ks < 2; ++ks) {
            const uint32_t kadd = st + ks * 32;
            uint32_t ah[2][4], al[2][4], bh[2][4], bl[2][4];
            #pragma unroll
            for (int i = 0; i < 2; ++i) {
                ldsm4(ah[i], kadd + offA[i]);
                ldsm4(al[i], kadd + ARR_B + offA[i]);
                ldsm4(bh[i], kadd + 2 * ARR_B + offB[i]);
                ldsm4(bl[i], kadd + 3 * ARR_B + offB[i]);
            }
            // main: f32-acc
            #pragma unroll
            for (int mf = 0; mf < 2; ++mf)
                #pragma unroll
                for (int nf = 0; nf < 4; ++nf) {
                    int np = nf >> 1, sub = nf & 1;
                    mmaF(accF[mf][nf], ah[mf], bh[np][sub], bh[np][sub + 2]);
                }
            // corrections: f16-acc (full-rate)
            #pragma unroll
            for (int mf = 0; mf < 2; ++mf)
                #pragma unroll
                for (int nf = 0; nf < 4; ++nf) {
                    int np = nf >> 1, sub = nf & 1;
                    mmaH(accH[mf][nf], ah[mf], bl[np][sub], bl[np][sub + 2]);
                }
            #pragma unroll
            for (int mf = 0; mf < 2; ++mf)
                #pragma unroll
                for (int nf = 0; nf < 4; ++nf) {
                    int np = nf >> 1, sub = nf & 1;
                    mmaH(accH[mf][nf], al[mf], bh[np][sub], bh[np][sub + 2]);
                }
        }
    }

    const int erow = lane >> 2;
    const int ecol = (lane & 3) << 1;
    #pragma unroll
    for (int mf = 0; mf < 2; ++mf) {
        #pragma unroll
        for (int nf = 0; nf < 4; ++nf) {
            int row = rowBase + m0 + mf * 16 + erow;
            int col = colBase + n0 + nf * 8 + ecol;
            float2 c01 = h2f2(accH[mf][nf][0]);
            float2 c23 = h2f2(accH[mf][nf][1]);
            #pragma unroll
            for (int half = 0; half < 2; ++half) {
                int r = row + half * 8;
                float ox = accF[mf][nf][half * 2 + 0] + (half ? c23.x : c01.x);
                float oy = accF[mf][nf][half * 2 + 1] + (half ? c23.y : c01.y);
                if (BIAS) {
                    float2 bv = *(const float2*)&bias[col];
                    ox += bv.x; oy += bv.y;
                }
                if (RES) {
                    float2 rv = *(const float2*)&res[(size_t)r * ldr + col];
                    ox += rv.x; oy += rv.y;
                }
                if (RELU) { ox = fmaxf(ox, 0.f); oy = fmaxf(oy, 0.f); }
                if (SPLIT) {
                    uint32_t wl;
                    uint32_t wh = splitpack(ox, oy, wl);
                    *(uint32_t*)&Chi[(size_t)r * ldc + col] = wh;
                    *(uint32_t*)&Clo[(size_t)r * ldc + col] = wl;
                } else {
                    float2 o; o.x = ox; o.y = oy;
                    *(float2*)&C[(size_t)r * ldc + col] = o;
                }
            }
        }
    }
}

// ---------------- fused flash attention (fp16x3 MMA, online softmax) ----------------
#define AROWH 72
#define FA_Q0 0
#define FA_Q1 9216
#define FA_K0 18432
#define FA_K1 27648
#define FA_V0 36864
#define FA_V1 46080
#define FA_SMEM 55296

__global__ void __launch_bounds__(128, 3) flash_attn_k(
    const h16* __restrict__ qkvhi, const h16* __restrict__ qkvlo,
    h16* __restrict__ atthi, h16* __restrict__ attlo)
{
    extern __shared__ __align__(16) char fsm[];
    const uint32_t sb = smem_u32(fsm);
    const int tid = threadIdx.x, lane = tid & 31, warp = tid >> 5;
    const int bh = blockIdx.y;
    const int b = bh >> 4, h = bh & 15;
    const int row0 = blockIdx.x * 64;
    const size_t qbase = (size_t)b * Tt * 3072 + h * 64;
    const size_t kbase = qbase + 1024;
    const size_t vbase = qbase + 2048;

    #pragma unroll
    for (int p = 0; p < 4; ++p) {
        int idx = tid + p * 128;
        int r = idx >> 3, c8 = (idx & 7) * 8;
        *(uint4*)(fsm + FA_Q0 + (r * AROWH + c8) * 2) =
            *(const uint4*)(qkvhi + qbase + (size_t)(row0 + r) * 3072 + c8);
        *(uint4*)(fsm + FA_Q1 + (r * AROWH + c8) * 2) =
            *(const uint4*)(qkvlo + qbase + (size_t)(row0 + r) * 3072 + c8);
    }

    const int m0 = warp * 16;
    const int lr16 = lane & 15, lk8 = (lane >> 4) << 3;
    const int g = lane >> 2;
    const int ec = (lane & 3) << 1;
    const float SCL = 0.125f * 1.4426950408889634f;

    float m_[2] = { -INFINITY, -INFINITY };
    float l_[2] = { 0.f, 0.f };
    float oacc[8][4];
    #pragma unroll
    for (int i = 0; i < 8; ++i)
        #pragma unroll
        for (int q = 0; q < 4; ++q) oacc[i][q] = 0.f;

    for (int j0 = 0; j0 <= row0; j0 += 64) {
        __syncthreads();
        #pragma unroll
        for (int p = 0; p < 4; ++p) {
            int idx = tid + p * 128;
            int r = idx >> 3, c8 = (idx & 7) * 8;
            *(uint4*)(fsm + FA_K0 + (r * AROWH + c8) * 2) =
                *(const uint4*)(qkvhi + kbase + (size_t)(j0 + r) * 3072 + c8);
            *(uint4*)(fsm + FA_K1 + (r * AROWH + c8) * 2) =
                *(const uint4*)(qkvlo + kbase + (size_t)(j0 + r) * 3072 + c8);
            *(uint4*)(fsm + FA_V0 + (r * AROWH + c8) * 2) =
                *(const uint4*)(qkvhi + vbase + (size_t)(j0 + r) * 3072 + c8);
            *(uint4*)(fsm + FA_V1 + (r * AROWH + c8) * 2) =
                *(const uint4*)(qkvlo + vbase + (size_t)(j0 + r) * 3072 + c8);
        }
        __syncthreads();

        float sacc[8][4];
        #pragma unroll
        for (int i = 0; i < 8; ++i)
            #pragma unroll
            for (int q = 0; q < 4; ++q) sacc[i][q] = 0.f;

        #pragma unroll
        for (int ks = 0; ks < 4; ++ks) {
            uint32_t ah[4], al[4];
            uint32_t aoff = ((m0 + lr16) * AROWH + ks * 16 + lk8) * 2;
            ldsm4(ah, sb + FA_Q0 + aoff);
            ldsm4(al, sb + FA_Q1 + aoff);
            uint32_t kh[4][4], kl[4][4];
            #pragma unroll
            for (int np = 0; np < 4; ++np) {
                uint32_t boff = ((np * 16 + lr16) * AROWH + ks * 16 + lk8) * 2;
                ldsm4(kh[np], sb + FA_K0 + boff);
                ldsm4(kl[np], sb + FA_K1 + boff);
            }
            #pragma unroll
            for (int nf = 0; nf < 8; ++nf) {
                int np = nf >> 1, sub = nf & 1;
                mmaF(sacc[nf], ah, kh[np][sub], kh[np][sub + 2]);
            }
            #pragma unroll
            for (int nf = 0; nf < 8; ++nf) {
                int np = nf >> 1, sub = nf & 1;
                mmaF(sacc[nf], ah, kl[np][sub], kl[np][sub + 2]);
            }
            #pragma unroll
            for (int nf = 0; nf < 8; ++nf) {
                int np = nf >> 1, sub = nf & 1;
                mmaF(sacc[nf], al, kh[np][sub], kh[np][sub + 2]);
            }
        }

        const bool diag = (j0 == row0);
        float mx0 = -INFINITY, mx1 = -INFINITY;
        #pragma unroll
        for (int nf = 0; nf < 8; ++nf) {
            #pragma unroll
            for (int q = 0; q < 4; ++q) {
                float vsc = sacc[nf][q] * SCL;
                if (diag) {
                    int cc = nf * 8 + ec + (q & 1);
                    int rr = m0 + g + ((q >> 1) << 3);
                    if (cc > rr) vsc = -INFINITY;
                }
                sacc[nf][q] = vsc;
                if (q < 2) mx0 = fmaxf(mx0, vsc); else mx1 = fmaxf(mx1, vsc);
            }
        }
        mx0 = fmaxf(mx0, __shfl_xor_sync(0xffffffffu, mx0, 1));
        mx0 = fmaxf(mx0, __shfl_xor_sync(0xffffffffu, mx0, 2));
        mx1 = fmaxf(mx1, __shfl_xor_sync(0xffffffffu, mx1, 1));
        mx1 = fmaxf(mx1, __shfl_xor_sync(0xffffffffu, mx1, 2));

        float mn0 = fmaxf(m_[0], mx0), mn1 = fmaxf(m_[1], mx1);
        float a0 = ex2f(m_[0] - mn0), a1 = ex2f(m_[1] - mn1);
        m_[0] = mn0; m_[1] = mn1;

        float s0 = 0.f, s1 = 0.f;
        #pragma unroll
        for (int nf = 0; nf < 8; ++nf) {
            float p0 = ex2f(sacc[nf][0] - mn0);
            float p1 = ex2f(sacc[nf][1] - mn0);
            float p2 = ex2f(sacc[nf][2] - mn1);
            float p3 = ex2f(sacc[nf][3] - mn1);
            sacc[nf][0] = p0; sacc[nf][1] = p1; sacc[nf][2] = p2; sacc[nf][3] = p3;
            s0 += p0 + p1; s1 += p2 + p3;
        }
        l_[0] = l_[0] * a0 + s0;
        l_[1] = l_[1] * a1 + s1;
        #pragma unroll
        for (int nf = 0; nf < 8; ++nf) {
            oacc[nf][0] *= a0; oacc[nf][1] *= a0;
            oacc[nf][2] *= a1; oacc[nf][3] *= a1;
        }

        uint32_t pah[4][4], pal[4][4];
        #pragma unroll
        for (int kf = 0; kf < 4; ++kf) {
            pah[kf][0] = splitpack(sacc[2*kf][0],   sacc[2*kf][1],   pal[kf][0]);
            pah[kf][1] = splitpack(sacc[2*kf][2],   sacc[2*kf][3],   pal[kf][1]);
            pah[kf][2] = splitpack(sacc[2*kf+1][0], sacc[2*kf+1][1], pal[kf][2]);
            pah[kf][3] = splitpack(sacc[2*kf+1][2], sacc[2*kf+1][3], pal[kf][3]);
        }

        #pragma unroll
        for (int kf = 0; kf < 4; ++kf) {
            uint32_t vh[4][4], vl[4][4];
            #pragma unroll
            for (int np = 0; np < 4; ++np) {
                uint32_t boff = ((kf * 16 + lr16) * AROWH + np * 16 + lk8) * 2;
                ldsm4t(vh[np], sb + FA_V0 + boff);
                ldsm4t(vl[np], sb + FA_V1 + boff);
            }
            #pragma unroll
            for (int nf = 0; nf < 8; ++nf) {
                int np = nf >> 1, sub = nf & 1;
                mmaF(oacc[nf], pah[kf], vh[np][sub * 2], vh[np][sub * 2 + 1]);
            }
            #pragma unroll
            for (int nf = 0; nf < 8; ++nf) {
                int np = nf >> 1, sub = nf & 1;
                mmaF(oacc[nf], pah[kf], vl[np][sub * 2], vl[np][sub * 2 + 1]);
            }
            #pragma unroll
            for (int nf = 0; nf < 8; ++nf) {
                int np = nf >> 1, sub = nf & 1;
                mmaF(oacc[nf], pal[kf], vh[np][sub * 2], vh[np][sub * 2 + 1]);
            }
        }
    }

    float l0 = l_[0], l1 = l_[1];
    l0 += __shfl_xor_sync(0xffffffffu, l0, 1);
    l0 += __shfl_xor_sync(0xffffffffu, l0, 2);
    l1 += __shfl_xor_sync(0xffffffffu, l1, 1);
    l1 += __shfl_xor_sync(0xffffffffu, l1, 2);
    float inv0 = 1.0f / l0, inv1 = 1.0f / l1;

    #pragma unroll
    for (int nf = 0; nf < 8; ++nf) {
        int col = h * 64 + nf * 8 + ec;
        size_t r0 = (size_t)b * Tt + row0 + m0 + g;
        uint32_t wl;
        uint32_t wh = splitpack(oacc[nf][0] * inv0, oacc[nf][1] * inv0, wl);
        *(uint32_t*)&atthi[r0 * Cc + col] = wh;
        *(uint32_t*)&attlo[r0 * Cc + col] = wl;
        wh = splitpack(oacc[nf][2] * inv1, oacc[nf][3] * inv1, wl);
        *(uint32_t*)&atthi[(r0 + 8) * Cc + col] = wh;
        *(uint32_t*)&attlo[(r0 + 8) * Cc + col] = wl;
    }
}

// ---------------- loss ----------------
__global__ void loss_rows_k(const float* __restrict__ logits, const int* __restrict__ targets,
                            float* __restrict__ rowloss) {
    __shared__ float buf[256];
    const float* L = logits + (size_t)blockIdx.x * Vv;
    int tid = threadIdx.x;
    const int V4 = Vv / 4;
    float m = -INFINITY;
    for (int j = tid; j < V4; j += 256) {
        float4 v = ((const float4*)L)[j];
        m = fmaxf(m, fmaxf(fmaxf(v.x, v.y), fmaxf(v.z, v.w)));
    }
    m = block_reduce(m, buf, true);
    float s = 0.f;
    for (int j = tid; j < V4; j += 256) {
        float4 v = ((const float4*)L)[j];
        s += expf(v.x - m) + expf(v.y - m) + expf(v.z - m) + expf(v.w - m);
    }
    s = block_reduce(s, buf, false);
    if (tid == 0) rowloss[blockIdx.x] = logf(s) + m - L[targets[blockIdx.x]];
}

__global__ void loss_reduce_k(const float* __restrict__ rowloss, float* __restrict__ out) {
    __shared__ float buf[256];
    int tid = threadIdx.x;
    float s = 0.f;
    for (int j = tid; j < Mm; j += 256) s += rowloss[j];
    s = block_reduce(s, buf, false);
    if (tid == 0) out[0] = s / (float)Mm;
}

// ---------------- launch ----------------
extern "C" void kernel_launch(void* const* d_in, const int* in_sizes, int n_in,
                              void* d_out, int out_size)
{
    const int*   idx     = (const int*)d_in[0];
    const int*   targets = (const int*)d_in[1];
    const float* tok_emb = (const float*)d_in[2];
    const float* pos_emb = (const float*)d_in[3];
    const float* ln1_g   = (const float*)d_in[4];
    const float* ln1_b   = (const float*)d_in[5];
    const float* Wq      = (const float*)d_in[6];
    const float* Wk      = (const float*)d_in[7];
    const float* Wv      = (const float*)d_in[8];
    const float* Wo      = (const float*)d_in[9];
    const float* bo      = (const float*)d_in[10];
    const float* ln2_g   = (const float*)d_in[11];
    const float* ln2_b   = (const float*)d_in[12];
    const float* W1      = (const float*)d_in[13];
    const float* b1      = (const float*)d_in[14];
    const float* W2      = (const float*)d_in[15];
    const float* b2      = (const float*)d_in[16];
    const float* lnf_g   = (const float*)d_in[17];
    const float* lnf_b   = (const float*)d_in[18];
    const float* Wlm     = (const float*)d_in[19];
    const float* blm     = (const float*)d_in[20];
    float* out = (float*)d_out;

    float *px, *prl;
    h16 *phhi, *phlo, *pqkvhi, *pqkvlo, *patthi, *pattlo, *pffhi, *pfflo, *pwhi, *pwlo;
    cudaGetSymbolAddress((void**)&px,     g_x);
    cudaGetSymbolAddress((void**)&prl,    g_rowloss);
    cudaGetSymbolAddress((void**)&phhi,   g_hhi);
    cudaGetSymbolAddress((void**)&phlo,   g_hlo);
    cudaGetSymbolAddress((void**)&pqkvhi, g_qkvhi);
    cudaGetSymbolAddress((void**)&pqkvlo, g_qkvlo);
    cudaGetSymbolAddress((void**)&patthi, g_atthi);
    cudaGetSymbolAddress((void**)&pattlo, g_attlo);
    cudaGetSymbolAddress((void**)&pffhi,  g_ffhhi);
    cudaGetSymbolAddress((void**)&pfflo,  g_ffhlo);
    cudaGetSymbolAddress((void**)&pwhi,   g_whi);
    cudaGetSymbolAddress((void**)&pwlo,   g_wlo);

    cudaFuncSetAttribute(gemm_tc<true,false,false,false>, cudaFuncAttributeMaxDynamicSharedMemorySize, GEMM_SMEM);
    cudaFuncSetAttribute(gemm_tc<false,true,true,false>,  cudaFuncAttributeMaxDynamicSharedMemorySize, GEMM_SMEM);
    cudaFuncSetAttribute(gemm_tc<true,true,false,true>,   cudaFuncAttributeMaxDynamicSharedMemorySize, GEMM_SMEM);
    cudaFuncSetAttribute(gemm_tc<false,true,false,false>, cudaFuncAttributeMaxDynamicSharedMemorySize, GEMM_SMEM);
    cudaFuncSetAttribute(flash_attn_k, cudaFuncAttributeMaxDynamicSharedMemorySize, FA_SMEM);

    embed_k<<<(Mm * Cc / 4 + 255) / 256, 256>>>(idx, tok_emb, pos_emb, px);

    dim3 gQKV(3072 / 128, Mm / 128);    // 24 x 32
    dim3 gC(Cc / 128, Mm / 128);        // 8 x 32
    dim3 gF(FFd / 128, Mm / 128);       // 32 x 32
    dim3 gVh(Vv / 128, Mm / 128);       // 393 x 32
    dim3 gFA(Tt / 64, Bb * Hh);         // 16 x 64

    for (int l = 0; l < Ll; ++l) {
        const size_t oCC = (size_t)l * Cc * Cc;
        const size_t oC  = (size_t)l * Cc;
        const size_t oCF = (size_t)l * Cc * FFd;
        const size_t oF  = (size_t)l * FFd;

        layernorm_split_k<<<Mm, 256>>>(px, ln1_g + oC, ln1_b + oC, phhi, phlo);
        conv_wqkv_k<<<dim3(Cc / 32, Cc / 32, 3), 256>>>(Wq + oCC, Wk + oCC, Wv + oCC,
                                                        pwhi, pwlo);
        gemm_tc<true,false,false,false><<<gQKV, 512, GEMM_SMEM>>>(
            Cc, phhi, phlo, pwhi, pwlo, nullptr, nullptr, 0,
            nullptr, pqkvhi, pqkvlo, 3072);

        flash_attn_k<<<gFA, 128, FA_SMEM>>>(pqkvhi, pqkvlo, patthi, pattlo);

        conv_wT_k<<<dim3(Cc / 32, Cc / 32), 256>>>(Wo + oCC, Cc, Cc, 0, pwhi, pwlo);
        gemm_tc<false,true,true,false><<<gC, 512, GEMM_SMEM>>>(
            Cc, patthi, pattlo, pwhi, pwlo, bo + oC, px, Cc,
            px, nullptr, nullptr, Cc);

        layernorm_split_k<<<Mm, 256>>>(px, ln2_g + oC, ln2_b + oC, phhi, phlo);
        conv_wT_k<<<dim3(FFd / 32, Cc / 32), 256>>>(W1 + oCF, Cc, FFd, 0, pwhi, pwlo);
        gemm_tc<true,true,false,true><<<gF, 512, GEMM_SMEM>>>(
            Cc, phhi, phlo, pwhi, pwlo, b1 + oF, nullptr, 0,
            nullptr, pffhi, pfflo, FFd);

        conv_wT_k<<<dim3(Cc / 32, FFd / 32), 256>>>(W2 + oCF, FFd, Cc, 0, pwhi, pwlo);
        gemm_tc<false,true,true,false><<<gC, 512, GEMM_SMEM>>>(
            FFd, pffhi, pfflo, pwhi, pwlo, b2 + oC, px, Cc,
            px, nullptr, nullptr, Cc);
    }

    // final LN + LM head -> logits into d_out
    layernorm_split_k<<<Mm, 256>>>(px, lnf_g, lnf_b, phhi, phlo);
    conv_wT_k<<<dim3(Vv / 32, Cc / 32), 256>>>(Wlm, Cc, Vv, 0, pwhi, pwlo);
    gemm_tc<false,true,false,false><<<gVh, 512, GEMM_SMEM>>>(
        Cc, phhi, phlo, pwhi, pwlo, blm, nullptr, 0,
        out, nullptr, nullptr, Vv);

    long long logitsN = (long long)Mm * Vv;
    if ((long long)out_size > logitsN) {
        loss_rows_k<<<Mm, 256>>>(out, targets, prl);
        loss_reduce_k<<<1, 256>>>(prl, out + logitsN);
    }
}